// round 12
// baseline (speedup 1.0000x reference)
#include <cuda_runtime.h>
#include <cuda_fp16.h>
#include <math.h>
#include <stdint.h>

// Problem constants
#define BATCH 2
#define CH    512
#define NSP   4096
#define C3    1536
#define NGRP  32
#define GSIZE (16*NSP)

// ---------------- scratch ----------------
__device__ __half g_seqh [(size_t)BATCH * NSP * CH];
__device__ __half g_qkvh [(size_t)BATCH * NSP * C3];
__device__ __half g_ph   [(size_t)BATCH * NSP * NSP];
__device__ __half g_vth  [(size_t)BATCH * CH * NSP];
__device__ __half g_attnh[(size_t)BATCH * NSP * CH];
__device__ __half g_qkvWh[(size_t)C3 * CH];
__device__ __half g_projWh[(size_t)CH * CH];
__device__ float  g_scor [(size_t)BATCH * NSP * NSP];
__device__ float  g_stats[BATCH * NGRP * 2];

// ---------------- helpers ----------------
__inline__ __device__ float warpSum(float v) {
    #pragma unroll
    for (int o = 16; o > 0; o >>= 1) v += __shfl_xor_sync(0xffffffffu, v, o);
    return v;
}
__inline__ __device__ float warpMax(float v) {
    #pragma unroll
    for (int o = 16; o > 0; o >>= 1) v = fmaxf(v, __shfl_xor_sync(0xffffffffu, v, o));
    return v;
}
__device__ __forceinline__ uint32_t smem_u32(const void* p) {
    uint32_t a;
    asm("{ .reg .u64 t; cvta.to.shared.u64 t, %1; cvt.u32.u64 %0, t; }" : "=r"(a) : "l"(p));
    return a;
}

// ---------------- GroupNorm stats ----------------
__global__ void gn_stats_kernel(const float* __restrict__ x, float* __restrict__ stats) {
    int bg = blockIdx.x;
    const float* p = x + (size_t)bg * GSIZE;
    float s = 0.f, ss = 0.f;
    for (int i = threadIdx.x; i < GSIZE; i += 256) {
        float v = p[i];
        s += v; ss += v * v;
    }
    s = warpSum(s); ss = warpSum(ss);
    __shared__ float shs[8], shss[8];
    int w = threadIdx.x >> 5, l = threadIdx.x & 31;
    if (l == 0) { shs[w] = s; shss[w] = ss; }
    __syncthreads();
    if (threadIdx.x == 0) {
        float S = 0.f, SS = 0.f;
        #pragma unroll
        for (int i = 0; i < 8; i++) { S += shs[i]; SS += shss[i]; }
        float mean = S * (1.f / GSIZE);
        float var  = SS * (1.f / GSIZE) - mean * mean;
        stats[2 * bg]     = mean;
        stats[2 * bg + 1] = rsqrtf(var + 1e-6f);
    }
}

// ---------------- GroupNorm apply + transpose -> half [b, n, c] ----------------
__global__ void gn_apply_kernel(const float* __restrict__ x,
                                const float* __restrict__ stats,
                                const float* __restrict__ gw,
                                const float* __restrict__ gb,
                                __half* __restrict__ seq) {
    __shared__ float t[32][33];
    int n0 = blockIdx.x * 32, c0 = blockIdx.y * 32, b = blockIdx.z;
    int tx = threadIdx.x, ty = threadIdx.y;
    #pragma unroll
    for (int j = 0; j < 4; j++) {
        int c = c0 + ty + j * 8;
        int bg = b * NGRP + (c >> 4);
        float mean = stats[2 * bg], rstd = stats[2 * bg + 1];
        float wv = gw[c] * rstd;
        float bv = gb[c] - mean * wv;
        float v = x[((size_t)(b * CH + c)) * NSP + n0 + tx];
        t[ty + j * 8][tx] = v * wv + bv;
    }
    __syncthreads();
    #pragma unroll
    for (int j = 0; j < 4; j++) {
        int n = n0 + ty + j * 8;
        seq[((size_t)(b * NSP + n)) * CH + c0 + tx] = __float2half(t[tx][ty + j * 8]);
    }
}

// ---------------- weight conversion fp32 -> fp16 ----------------
__global__ void wconv_kernel(const float* __restrict__ qkvW, const float* __restrict__ projW,
                             __half* __restrict__ qkvWh, __half* __restrict__ projWh) {
    int i = blockIdx.x * 256 + threadIdx.x;
    #pragma unroll
    for (int r = 0; r < 4; r++) {
        int idx = i * 4 + r;
        if (idx < C3 * CH) qkvWh[idx] = __float2half(qkvW[idx]);
        if (idx < CH * CH) projWh[idx] = __float2half(projW[idx]);
    }
}

// ---------------- V transpose ----------------
__global__ void vtrans_kernel(const __half* __restrict__ qkv, __half* __restrict__ vt) {
    __shared__ __half t[32][33];
    int n0 = blockIdx.x * 32, c0 = blockIdx.y * 32, b = blockIdx.z;
    int tx = threadIdx.x, ty = threadIdx.y;
    #pragma unroll
    for (int j = 0; j < 4; j++) {
        int n = n0 + ty + j * 8;
        t[ty + j * 8][tx] = qkv[((size_t)(b * NSP + n)) * C3 + 2 * CH + c0 + tx];
    }
    __syncthreads();
    #pragma unroll
    for (int j = 0; j < 4; j++) {
        int c = c0 + ty + j * 8;
        vt[((size_t)(b * CH + c)) * NSP + n0 + tx] = t[tx][ty + j * 8];
    }
}

// ---------------- fp16 NT GEMM: mma.sync m16n8k16 + ldmatrix -------------------
// BM=BN=128, BK=64; 128 threads = 4 warps (2m x 2n), warp tile 64x64.
// MODE: 0 = half out, 1 = float out, 2 = float out transposed + residual add.
// smem row stride 72 halfs (144B): bank-quad r*9 mod 8 = r mod 8 -> conflict-free.
// 3-stage cp.async ring; 2 CTAs/SM (216KB smem).
#define HROW 72
#define STAGE_B 36864         // (128*144)*2 tensors
#define NSTAGE 3
#define HG_SMEM (NSTAGE * STAGE_B)   // 110592

__device__ __forceinline__ void hfill(const __half* __restrict__ A,
                                      const __half* __restrict__ B,
                                      int lda, int ldb, int k0,
                                      uint32_t sbase, int stage, int tid) {
    uint32_t sa = sbase + stage * STAGE_B;
    uint32_t sb = sa + 18432;
    #pragma unroll
    for (int i = 0; i < 8; i++) {
        int idx = tid + 128 * i;
        int row = idx >> 3, c = idx & 7;
        const __half* g = A + (long long)row * lda + k0 + c * 8;
        asm volatile("cp.async.cg.shared.global [%0], [%1], 16;"
                     :: "r"(sa + row * 144 + c * 16), "l"(g));
    }
    #pragma unroll
    for (int i = 0; i < 8; i++) {
        int idx = tid + 128 * i;
        int row = idx >> 3, c = idx & 7;
        const __half* g = B + (long long)row * ldb + k0 + c * 8;
        asm volatile("cp.async.cg.shared.global [%0], [%1], 16;"
                     :: "r"(sb + row * 144 + c * 16), "l"(g));
    }
    asm volatile("cp.async.commit_group;" ::: "memory");
}

template <int MODE>
__global__ void __launch_bounds__(128, 2) hgemm(
    const __half* __restrict__ A, int lda, long long sA,
    const __half* __restrict__ B, int ldb, long long sB,
    void* __restrict__ Cv, int ldc, long long sC,
    int K, float alpha, const float* __restrict__ bias,
    const float* __restrict__ xres) {

    extern __shared__ char smem[];
    uint32_t sbase = smem_u32(smem);

    const int tid = threadIdx.x;
    const int lane = tid & 31;
    const int wid = tid >> 5;
    const int warpM = wid >> 1;          // 0..1
    const int warpN = wid & 1;           // 0..1
    const int g = lane >> 2, t4 = lane & 3;
    const int l8 = lane & 7, lm = lane >> 3;

    A += blockIdx.z * sA + (long long)blockIdx.y * 128 * lda;
    B += blockIdx.z * sB + (long long)blockIdx.x * 128 * ldb;

    const uint32_t a_off = (uint32_t)(((lm & 1) * 8 + l8) * 144 + (lm >> 1) * 16)
                         + (uint32_t)(warpM * 64) * 144;
    const uint32_t b_off = (uint32_t)(((lm >> 1) * 8 + l8) * 144 + (lm & 1) * 16)
                         + (uint32_t)(warpN * 64) * 144;

    float acc[4][8][4];
    #pragma unroll
    for (int i = 0; i < 4; i++)
        #pragma unroll
        for (int j = 0; j < 8; j++)
            #pragma unroll
            for (int q = 0; q < 4; q++) acc[i][j][q] = 0.f;

    const int S = K / 64;

    // prologue: 2 groups in flight
    hfill(A, B, lda, ldb, 0, sbase, 0, tid);
    hfill(A, B, lda, ldb, 64, sbase, 1, tid);

    int stage = 0;
    #pragma unroll 1
    for (int s = 0; s < S; s++) {
        if (s + 1 < S) asm volatile("cp.async.wait_group 1;" ::: "memory");
        else           asm volatile("cp.async.wait_group 0;" ::: "memory");
        __syncthreads();
        if (s + 2 < S) {
            int fstage = stage + 2; if (fstage >= NSTAGE) fstage -= NSTAGE;
            hfill(A, B, lda, ldb, (s + 2) * 64, sbase, fstage, tid);
        }

        const uint32_t sAb = sbase + stage * STAGE_B;
        const uint32_t sBb = sAb + 18432;

        #pragma unroll
        for (int kk = 0; kk < 4; kk++) {
            const uint32_t kadd = kk * 32;
            uint32_t af[4][4];
            #pragma unroll
            for (int mf = 0; mf < 4; mf++) {
                asm volatile("ldmatrix.sync.aligned.m8n8.x4.shared.b16 {%0,%1,%2,%3}, [%4];"
                    : "=r"(af[mf][0]), "=r"(af[mf][1]), "=r"(af[mf][2]), "=r"(af[mf][3])
                    : "r"(sAb + a_off + mf * 2304 + kadd));
            }
            uint32_t bf[8][2];
            #pragma unroll
            for (int p = 0; p < 4; p++) {
                asm volatile("ldmatrix.sync.aligned.m8n8.x4.shared.b16 {%0,%1,%2,%3}, [%4];"
                    : "=r"(bf[2*p][0]), "=r"(bf[2*p][1]), "=r"(bf[2*p+1][0]), "=r"(bf[2*p+1][1])
                    : "r"(sBb + b_off + p * 2304 + kadd));
            }
            #pragma unroll
            for (int mf = 0; mf < 4; mf++)
                #pragma unroll
                for (int nf = 0; nf < 8; nf++) {
                    asm volatile(
                        "mma.sync.aligned.m16n8k16.row.col.f32.f16.f16.f32 "
                        "{%0,%1,%2,%3}, {%4,%5,%6,%7}, {%8,%9}, {%0,%1,%2,%3};"
                        : "+f"(acc[mf][nf][0]), "+f"(acc[mf][nf][1]),
                          "+f"(acc[mf][nf][2]), "+f"(acc[mf][nf][3])
                        : "r"(af[mf][0]), "r"(af[mf][1]), "r"(af[mf][2]), "r"(af[mf][3]),
                          "r"(bf[nf][0]), "r"(bf[nf][1]));
                }
        }
        if (++stage >= NSTAGE) stage = 0;
    }

    const float* bp = bias ? bias + blockIdx.x * 128 : nullptr;
    #pragma unroll
    for (int mf = 0; mf < 4; mf++) {
        const int row = warpM * 64 + mf * 16 + g;
        #pragma unroll
        for (int nf = 0; nf < 8; nf++) {
            const int col = warpN * 64 + nf * 8 + 2 * t4;
            float b0 = 0.f, b1 = 0.f;
            if (bp) { b0 = bp[col]; b1 = bp[col + 1]; }
            float v00 = alpha * acc[mf][nf][0] + b0;
            float v01 = alpha * acc[mf][nf][1] + b1;
            float v10 = alpha * acc[mf][nf][2] + b0;
            float v11 = alpha * acc[mf][nf][3] + b1;
            if (MODE == 0) {
                __half* C = (__half*)Cv + blockIdx.z * sC
                          + (long long)blockIdx.y * 128 * ldc + blockIdx.x * 128;
                *(__half2*)(C + (long long)row * ldc + col)       = __floats2half2_rn(v00, v01);
                *(__half2*)(C + (long long)(row + 8) * ldc + col) = __floats2half2_rn(v10, v11);
            } else if (MODE == 1) {
                float* C = (float*)Cv + blockIdx.z * sC
                         + (long long)blockIdx.y * 128 * ldc + blockIdx.x * 128;
                float2 u0 = { v00, v01 }, u1 = { v10, v11 };
                *(float2*)(C + (long long)row * ldc + col)       = u0;
                *(float2*)(C + (long long)(row + 8) * ldc + col) = u1;
            } else {
                // MODE 2: transposed residual write: out[b, c, n] = x[b, c, n] + v
                const int rowg = blockIdx.y * 128 + row;
                const int b  = rowg >> 12;        // / NSP
                const int n  = rowg & (NSP - 1);
                const int c0 = blockIdx.x * 128 + col;
                float* out = (float*)Cv;
                size_t base = (size_t)b * CH * NSP + n;
                size_t i00 = base + (size_t)c0 * NSP;
                size_t i01 = base + (size_t)(c0 + 1) * NSP;
                out[i00]     = xres[i00]     + v00;
                out[i01]     = xres[i01]     + v01;
                out[i00 + 8] = xres[i00 + 8] + v10;
                out[i01 + 8] = xres[i01 + 8] + v11;
            }
        }
    }
}

// ---------------- row softmax fp32 -> half P ----------------
__global__ void __launch_bounds__(256) softmax_kernel(const float* __restrict__ S,
                                                      __half* __restrict__ P) {
    const float* p = S + (size_t)blockIdx.x * NSP;
    __half2* o = (__half2*)(P + (size_t)blockIdx.x * NSP);
    float4 v[4];
    const int t = threadIdx.x;
    float m = -1e30f;
    #pragma unroll
    for (int i = 0; i < 4; i++) {
        v[i] = ((const float4*)p)[t + 256 * i];
        m = fmaxf(m, fmaxf(fmaxf(v[i].x, v[i].y), fmaxf(v[i].z, v[i].w)));
    }
    __shared__ float red[8];
    int w = t >> 5, l = t & 31;
    m = warpMax(m);
    if (l == 0) red[w] = m;
    __syncthreads();
    if (w == 0) {
        float tm = (l < 8) ? red[l] : -1e30f;
        tm = warpMax(tm);
        if (l == 0) red[0] = tm;
    }
    __syncthreads();
    m = red[0];
    __syncthreads();

    float s = 0.f;
    #pragma unroll
    for (int i = 0; i < 4; i++) {
        v[i].x = __expf(v[i].x - m);
        v[i].y = __expf(v[i].y - m);
        v[i].z = __expf(v[i].z - m);
        v[i].w = __expf(v[i].w - m);
        s += v[i].x + v[i].y + v[i].z + v[i].w;
    }
    s = warpSum(s);
    if (l == 0) red[w] = s;
    __syncthreads();
    if (w == 0) {
        float ts = (l < 8) ? red[l] : 0.f;
        ts = warpSum(ts);
        if (l == 0) red[0] = ts;
    }
    __syncthreads();
    float inv = __frcp_rn(red[0]);
    #pragma unroll
    for (int i = 0; i < 4; i++) {
        int base = (t + 256 * i) * 2;
        o[base]     = __floats2half2_rn(v[i].x * inv, v[i].y * inv);
        o[base + 1] = __floats2half2_rn(v[i].z * inv, v[i].w * inv);
    }
}

// ---------------- launch ----------------
extern "C" void kernel_launch(void* const* d_in, const int* in_sizes, int n_in,
                              void* d_out, int out_size) {
    const float* x     = (const float*)d_in[0];
    const float* gw    = (const float*)d_in[1];
    const float* gb    = (const float*)d_in[2];
    const float* qkvW  = (const float*)d_in[3];
    const float* qkvB  = (const float*)d_in[4];
    const float* projW = (const float*)d_in[5];
    const float* projB = (const float*)d_in[6];
    float* out = (float*)d_out;

    __half *seqh, *qkvh, *ph, *vth, *attnh, *qkvWh, *projWh;
    float *scor, *stats;
    cudaGetSymbolAddress((void**)&seqh,  g_seqh);
    cudaGetSymbolAddress((void**)&qkvh,  g_qkvh);
    cudaGetSymbolAddress((void**)&ph,    g_ph);
    cudaGetSymbolAddress((void**)&vth,   g_vth);
    cudaGetSymbolAddress((void**)&attnh, g_attnh);
    cudaGetSymbolAddress((void**)&qkvWh, g_qkvWh);
    cudaGetSymbolAddress((void**)&projWh,g_projWh);
    cudaGetSymbolAddress((void**)&scor,  g_scor);
    cudaGetSymbolAddress((void**)&stats, g_stats);

    static bool attr_done = false;
    if (!attr_done) {
        cudaFuncSetAttribute((const void*)hgemm<0>,
                             cudaFuncAttributeMaxDynamicSharedMemorySize, HG_SMEM);
        cudaFuncSetAttribute((const void*)hgemm<1>,
                             cudaFuncAttributeMaxDynamicSharedMemorySize, HG_SMEM);
        cudaFuncSetAttribute((const void*)hgemm<2>,
                             cudaFuncAttributeMaxDynamicSharedMemorySize, HG_SMEM);
        attr_done = true;
    }

    // 1. GroupNorm + weight conversion
    gn_stats_kernel<<<BATCH * NGRP, 256>>>(x, stats);
    wconv_kernel<<<C3 * CH / 1024, 256>>>(qkvW, projW, qkvWh, projWh);
    gn_apply_kernel<<<dim3(NSP / 32, CH / 32, BATCH), dim3(32, 8)>>>(x, stats, gw, gb, seqh);

    // 2. QKV projection -> half
    hgemm<0><<<dim3(C3 / 128, (BATCH * NSP) / 128, 1), 128, HG_SMEM>>>(
        seqh, CH, 0, qkvWh, CH, 0, qkvh, C3, 0, CH, 1.f, qkvB, nullptr);

    // 3. V transpose
    vtrans_kernel<<<dim3(NSP / 32, CH / 32, BATCH), dim3(32, 8)>>>(qkvh, vth);

    // 4. Scores: Q K^T * scale -> fp32
    const float scale = 0.044194173824159216f;
    hgemm<1><<<dim3(NSP / 128, NSP / 128, BATCH), 128, HG_SMEM>>>(
        qkvh, C3, (long long)NSP * C3,
        qkvh + CH, C3, (long long)NSP * C3,
        scor, NSP, (long long)NSP * NSP,
        CH, scale, nullptr, nullptr);

    // 5. Softmax -> half P
    softmax_kernel<<<BATCH * NSP, 256>>>(scor, ph);

    // 6. O = P V^T -> half
    hgemm<0><<<dim3(CH / 128, NSP / 128, BATCH), 128, HG_SMEM>>>(
        ph, NSP, (long long)NSP * NSP,
        vth, NSP, (long long)CH * NSP,
        attnh, CH, (long long)NSP * CH,
        NSP, 1.f, nullptr, nullptr);

    // 7. Output projection + residual + transpose, fused -> out [b, c, h, w, d]
    hgemm<2><<<dim3(CH / 128, (BATCH * NSP) / 128, 1), 128, HG_SMEM>>>(
        attnh, CH, 0, projWh, CH, 0, out, CH, (long long)CH * NSP, CH, 1.f, projB, x);
}

// round 14
// speedup vs baseline: 1.0480x; 1.0480x over previous
#include <cuda_runtime.h>
#include <cuda_fp16.h>
#include <math.h>
#include <stdint.h>

// Problem constants
#define BATCH 2
#define CH    512
#define NSP   4096
#define C3    1536
#define NGRP  32
#define GSIZE (16*NSP)

// ---------------- scratch ----------------
__device__ __half g_seqh [(size_t)BATCH * NSP * CH];
__device__ __half g_qkvh [(size_t)BATCH * NSP * C3];
__device__ __half g_ph   [(size_t)BATCH * NSP * NSP];
__device__ __half g_vth  [(size_t)BATCH * CH * NSP];
__device__ __half g_attnh[(size_t)BATCH * NSP * CH];
__device__ __half g_qkvWh[(size_t)C3 * CH];
__device__ __half g_projWh[(size_t)CH * CH];
__device__ float  g_scor [(size_t)BATCH * NSP * NSP];
__device__ float  g_stats[BATCH * NGRP * 2];

// ---------------- helpers ----------------
__inline__ __device__ float warpSum(float v) {
    #pragma unroll
    for (int o = 16; o > 0; o >>= 1) v += __shfl_xor_sync(0xffffffffu, v, o);
    return v;
}
__inline__ __device__ float warpMax(float v) {
    #pragma unroll
    for (int o = 16; o > 0; o >>= 1) v = fmaxf(v, __shfl_xor_sync(0xffffffffu, v, o));
    return v;
}
__device__ __forceinline__ uint32_t smem_u32(const void* p) {
    uint32_t a;
    asm("{ .reg .u64 t; cvta.to.shared.u64 t, %1; cvt.u32.u64 %0, t; }" : "=r"(a) : "l"(p));
    return a;
}

// ---------------- GroupNorm stats ----------------
__global__ void gn_stats_kernel(const float* __restrict__ x, float* __restrict__ stats) {
    int bg = blockIdx.x;
    const float* p = x + (size_t)bg * GSIZE;
    float s = 0.f, ss = 0.f;
    for (int i = threadIdx.x; i < GSIZE; i += 256) {
        float v = p[i];
        s += v; ss += v * v;
    }
    s = warpSum(s); ss = warpSum(ss);
    __shared__ float shs[8], shss[8];
    int w = threadIdx.x >> 5, l = threadIdx.x & 31;
    if (l == 0) { shs[w] = s; shss[w] = ss; }
    __syncthreads();
    if (threadIdx.x == 0) {
        float S = 0.f, SS = 0.f;
        #pragma unroll
        for (int i = 0; i < 8; i++) { S += shs[i]; SS += shss[i]; }
        float mean = S * (1.f / GSIZE);
        float var  = SS * (1.f / GSIZE) - mean * mean;
        stats[2 * bg]     = mean;
        stats[2 * bg + 1] = rsqrtf(var + 1e-6f);
    }
}

// ---------------- GroupNorm apply + transpose -> half [b, n, c] ----------------
__global__ void gn_apply_kernel(const float* __restrict__ x,
                                const float* __restrict__ stats,
                                const float* __restrict__ gw,
                                const float* __restrict__ gb,
                                __half* __restrict__ seq) {
    __shared__ float t[32][33];
    int n0 = blockIdx.x * 32, c0 = blockIdx.y * 32, b = blockIdx.z;
    int tx = threadIdx.x, ty = threadIdx.y;
    #pragma unroll
    for (int j = 0; j < 4; j++) {
        int c = c0 + ty + j * 8;
        int bg = b * NGRP + (c >> 4);
        float mean = stats[2 * bg], rstd = stats[2 * bg + 1];
        float wv = gw[c] * rstd;
        float bv = gb[c] - mean * wv;
        float v = x[((size_t)(b * CH + c)) * NSP + n0 + tx];
        t[ty + j * 8][tx] = v * wv + bv;
    }
    __syncthreads();
    #pragma unroll
    for (int j = 0; j < 4; j++) {
        int n = n0 + ty + j * 8;
        seq[((size_t)(b * NSP + n)) * CH + c0 + tx] = __float2half(t[tx][ty + j * 8]);
    }
}

// ---------------- weight conversion fp32 -> fp16 ----------------
__global__ void wconv_kernel(const float* __restrict__ qkvW, const float* __restrict__ projW,
                             __half* __restrict__ qkvWh, __half* __restrict__ projWh) {
    int i = blockIdx.x * 256 + threadIdx.x;
    #pragma unroll
    for (int r = 0; r < 4; r++) {
        int idx = i * 4 + r;
        if (idx < C3 * CH) qkvWh[idx] = __float2half(qkvW[idx]);
        if (idx < CH * CH) projWh[idx] = __float2half(projW[idx]);
    }
}

// ---------------- V transpose ----------------
__global__ void vtrans_kernel(const __half* __restrict__ qkv, __half* __restrict__ vt) {
    __shared__ __half t[32][33];
    int n0 = blockIdx.x * 32, c0 = blockIdx.y * 32, b = blockIdx.z;
    int tx = threadIdx.x, ty = threadIdx.y;
    #pragma unroll
    for (int j = 0; j < 4; j++) {
        int n = n0 + ty + j * 8;
        t[ty + j * 8][tx] = qkv[((size_t)(b * NSP + n)) * C3 + 2 * CH + c0 + tx];
    }
    __syncthreads();
    #pragma unroll
    for (int j = 0; j < 4; j++) {
        int c = c0 + ty + j * 8;
        vt[((size_t)(b * CH + c)) * NSP + n0 + tx] = t[tx][ty + j * 8];
    }
}

// ---------------- fp16 NT GEMM: mma.sync m16n8k16 + ldmatrix -------------------
// BM=BN=128, BK=32; 128 threads = 4 warps (2m x 2n), warp tile 64x64.  (R10 config)
// MODE: 0 = half out, 1 = float out, 2 = float out transposed + residual add.
// 4-stage cp.async ring; smem row stride 40 halfs (80B) conflict-free.
#define HROW 40
#define STAGE_B 20480         // A: 128*80 + B: 128*80
#define NSTAGE 4
#define HG_SMEM (NSTAGE * STAGE_B)   // 81920 -> 2 CTAs = 163840 <= 227KB

__device__ __forceinline__ void hfill(const __half* __restrict__ A,
                                      const __half* __restrict__ B,
                                      int lda, int ldb, int k0,
                                      uint32_t sbase, int stage, int tid) {
    uint32_t sa = sbase + stage * STAGE_B;
    uint32_t sb = sa + 10240;
    #pragma unroll
    for (int i = 0; i < 4; i++) {
        int idx = tid + 128 * i;
        int row = idx >> 2, c = idx & 3;
        const __half* g = A + (long long)row * lda + k0 + c * 8;
        asm volatile("cp.async.cg.shared.global [%0], [%1], 16;"
                     :: "r"(sa + row * 80 + c * 16), "l"(g));
    }
    #pragma unroll
    for (int i = 0; i < 4; i++) {
        int idx = tid + 128 * i;
        int row = idx >> 2, c = idx & 3;
        const __half* g = B + (long long)row * ldb + k0 + c * 8;
        asm volatile("cp.async.cg.shared.global [%0], [%1], 16;"
                     :: "r"(sb + row * 80 + c * 16), "l"(g));
    }
    asm volatile("cp.async.commit_group;" ::: "memory");
}

template <int MODE>
__global__ void __launch_bounds__(128, 2) hgemm(
    const __half* __restrict__ A, int lda, long long sA,
    const __half* __restrict__ B, int ldb, long long sB,
    void* __restrict__ Cv, int ldc, long long sC,
    int K, float alpha, const float* __restrict__ bias,
    const float* __restrict__ xres) {

    extern __shared__ char smem[];
    uint32_t sbase = smem_u32(smem);

    const int tid = threadIdx.x;
    const int lane = tid & 31;
    const int wid = tid >> 5;
    const int warpM = wid >> 1;          // 0..1
    const int warpN = wid & 1;           // 0..1
    const int g = lane >> 2, t4 = lane & 3;
    const int l8 = lane & 7, lm = lane >> 3;

    A += blockIdx.z * sA + (long long)blockIdx.y * 128 * lda;
    B += blockIdx.z * sB + (long long)blockIdx.x * 128 * ldb;

    const uint32_t a_off = (uint32_t)(((lm & 1) * 8 + l8) * 80 + (lm >> 1) * 16)
                         + (uint32_t)(warpM * 64) * 80;
    const uint32_t b_off = (uint32_t)(((lm >> 1) * 8 + l8) * 80 + (lm & 1) * 16)
                         + (uint32_t)(warpN * 64) * 80;

    float acc[4][8][4];
    #pragma unroll
    for (int i = 0; i < 4; i++)
        #pragma unroll
        for (int j = 0; j < 8; j++)
            #pragma unroll
            for (int q = 0; q < 4; q++) acc[i][j][q] = 0.f;

    const int S = K / 32;

    // prologue: 3 groups in flight
    #pragma unroll
    for (int s = 0; s < 3; s++)
        hfill(A, B, lda, ldb, s * 32, sbase, s, tid);

    int stage = 0;
    #pragma unroll 1
    for (int s = 0; s < S; s++) {
        const int rem = S - 1 - s;
        if (rem >= 2)      asm volatile("cp.async.wait_group 2;" ::: "memory");
        else if (rem == 1) asm volatile("cp.async.wait_group 1;" ::: "memory");
        else               asm volatile("cp.async.wait_group 0;" ::: "memory");
        __syncthreads();
        if (s + 3 < S) {
            int fstage = stage + 3; if (fstage >= NSTAGE) fstage -= NSTAGE;
            hfill(A, B, lda, ldb, (s + 3) * 32, sbase, fstage, tid);
        }

        const uint32_t sAb = sbase + stage * STAGE_B;
        const uint32_t sBb = sAb + 10240;

        #pragma unroll
        for (int kk = 0; kk < 2; kk++) {
            const uint32_t kadd = kk * 32;
            uint32_t af[4][4];
            #pragma unroll
            for (int mf = 0; mf < 4; mf++) {
                asm volatile("ldmatrix.sync.aligned.m8n8.x4.shared.b16 {%0,%1,%2,%3}, [%4];"
                    : "=r"(af[mf][0]), "=r"(af[mf][1]), "=r"(af[mf][2]), "=r"(af[mf][3])
                    : "r"(sAb + a_off + mf * 1280 + kadd));
            }
            uint32_t bf[8][2];
            #pragma unroll
            for (int p = 0; p < 4; p++) {
                asm volatile("ldmatrix.sync.aligned.m8n8.x4.shared.b16 {%0,%1,%2,%3}, [%4];"
                    : "=r"(bf[2*p][0]), "=r"(bf[2*p][1]), "=r"(bf[2*p+1][0]), "=r"(bf[2*p+1][1])
                    : "r"(sBb + b_off + p * 1280 + kadd));
            }
            #pragma unroll
            for (int mf = 0; mf < 4; mf++)
                #pragma unroll
                for (int nf = 0; nf < 8; nf++) {
                    asm volatile(
                        "mma.sync.aligned.m16n8k16.row.col.f32.f16.f16.f32 "
                        "{%0,%1,%2,%3}, {%4,%5,%6,%7}, {%8,%9}, {%0,%1,%2,%3};"
                        : "+f"(acc[mf][nf][0]), "+f"(acc[mf][nf][1]),
                          "+f"(acc[mf][nf][2]), "+f"(acc[mf][nf][3])
                        : "r"(af[mf][0]), "r"(af[mf][1]), "r"(af[mf][2]), "r"(af[mf][3]),
                          "r"(bf[nf][0]), "r"(bf[nf][1]));
                }
        }
        if (++stage >= NSTAGE) stage = 0;
    }

    const float* bp = bias ? bias + blockIdx.x * 128 : nullptr;
    #pragma unroll
    for (int mf = 0; mf < 4; mf++) {
        const int row = warpM * 64 + mf * 16 + g;
        #pragma unroll
        for (int nf = 0; nf < 8; nf++) {
            const int col = warpN * 64 + nf * 8 + 2 * t4;
            float b0 = 0.f, b1 = 0.f;
            if (bp) { b0 = bp[col]; b1 = bp[col + 1]; }
            float v00 = alpha * acc[mf][nf][0] + b0;
            float v01 = alpha * acc[mf][nf][1] + b1;
            float v10 = alpha * acc[mf][nf][2] + b0;
            float v11 = alpha * acc[mf][nf][3] + b1;
            if (MODE == 0) {
                __half* C = (__half*)Cv + blockIdx.z * sC
                          + (long long)blockIdx.y * 128 * ldc + blockIdx.x * 128;
                *(__half2*)(C + (long long)row * ldc + col)       = __floats2half2_rn(v00, v01);
                *(__half2*)(C + (long long)(row + 8) * ldc + col) = __floats2half2_rn(v10, v11);
            } else if (MODE == 1) {
                float* C = (float*)Cv + blockIdx.z * sC
                         + (long long)blockIdx.y * 128 * ldc + blockIdx.x * 128;
                float2 u0 = { v00, v01 }, u1 = { v10, v11 };
                *(float2*)(C + (long long)row * ldc + col)       = u0;
                *(float2*)(C + (long long)(row + 8) * ldc + col) = u1;
            } else {
                // MODE 2: transposed residual write: out[b, c, n] = x[b, c, n] + v
                const int rowg = blockIdx.y * 128 + row;
                const int b  = rowg >> 12;        // / NSP
                const int n  = rowg & (NSP - 1);
                const int c0 = blockIdx.x * 128 + col;
                float* out = (float*)Cv;
                size_t base = (size_t)b * CH * NSP + n;
                size_t i00 = base + (size_t)c0 * NSP;
                size_t i01 = base + (size_t)(c0 + 1) * NSP;
                out[i00]     = xres[i00]     + v00;
                out[i01]     = xres[i01]     + v01;
                out[i00 + 8] = xres[i00 + 8] + v10;
                out[i01 + 8] = xres[i01 + 8] + v11;
            }
        }
    }
}

// ---------------- row softmax fp32 -> half P ----------------
__global__ void __launch_bounds__(256) softmax_kernel(const float* __restrict__ S,
                                                      __half* __restrict__ P) {
    const float* p = S + (size_t)blockIdx.x * NSP;
    __half2* o = (__half2*)(P + (size_t)blockIdx.x * NSP);
    float4 v[4];
    const int t = threadIdx.x;
    float m = -1e30f;
    #pragma unroll
    for (int i = 0; i < 4; i++) {
        v[i] = ((const float4*)p)[t + 256 * i];
        m = fmaxf(m, fmaxf(fmaxf(v[i].x, v[i].y), fmaxf(v[i].z, v[i].w)));
    }
    __shared__ float red[8];
    int w = t >> 5, l = t & 31;
    m = warpMax(m);
    if (l == 0) red[w] = m;
    __syncthreads();
    if (w == 0) {
        float tm = (l < 8) ? red[l] : -1e30f;
        tm = warpMax(tm);
        if (l == 0) red[0] = tm;
    }
    __syncthreads();
    m = red[0];
    __syncthreads();

    float s = 0.f;
    #pragma unroll
    for (int i = 0; i < 4; i++) {
        v[i].x = __expf(v[i].x - m);
        v[i].y = __expf(v[i].y - m);
        v[i].z = __expf(v[i].z - m);
        v[i].w = __expf(v[i].w - m);
        s += v[i].x + v[i].y + v[i].z + v[i].w;
    }
    s = warpSum(s);
    if (l == 0) red[w] = s;
    __syncthreads();
    if (w == 0) {
        float ts = (l < 8) ? red[l] : 0.f;
        ts = warpSum(ts);
        if (l == 0) red[0] = ts;
    }
    __syncthreads();
    float inv = __frcp_rn(red[0]);
    #pragma unroll
    for (int i = 0; i < 4; i++) {
        int base = (t + 256 * i) * 2;
        o[base]     = __floats2half2_rn(v[i].x * inv, v[i].y * inv);
        o[base + 1] = __floats2half2_rn(v[i].z * inv, v[i].w * inv);
    }
}

// ---------------- launch ----------------
extern "C" void kernel_launch(void* const* d_in, const int* in_sizes, int n_in,
                              void* d_out, int out_size) {
    const float* x     = (const float*)d_in[0];
    const float* gw    = (const float*)d_in[1];
    const float* gb    = (const float*)d_in[2];
    const float* qkvW  = (const float*)d_in[3];
    const float* qkvB  = (const float*)d_in[4];
    const float* projW = (const float*)d_in[5];
    const float* projB = (const float*)d_in[6];
    float* out = (float*)d_out;

    __half *seqh, *qkvh, *ph, *vth, *attnh, *qkvWh, *projWh;
    float *scor, *stats;
    cudaGetSymbolAddress((void**)&seqh,  g_seqh);
    cudaGetSymbolAddress((void**)&qkvh,  g_qkvh);
    cudaGetSymbolAddress((void**)&ph,    g_ph);
    cudaGetSymbolAddress((void**)&vth,   g_vth);
    cudaGetSymbolAddress((void**)&attnh, g_attnh);
    cudaGetSymbolAddress((void**)&qkvWh, g_qkvWh);
    cudaGetSymbolAddress((void**)&projWh,g_projWh);
    cudaGetSymbolAddress((void**)&scor,  g_scor);
    cudaGetSymbolAddress((void**)&stats, g_stats);

    static bool attr_done = false;
    if (!attr_done) {
        cudaFuncSetAttribute((const void*)hgemm<0>,
                             cudaFuncAttributeMaxDynamicSharedMemorySize, HG_SMEM);
        cudaFuncSetAttribute((const void*)hgemm<1>,
                             cudaFuncAttributeMaxDynamicSharedMemorySize, HG_SMEM);
        cudaFuncSetAttribute((const void*)hgemm<2>,
                             cudaFuncAttributeMaxDynamicSharedMemorySize, HG_SMEM);
        attr_done = true;
    }

    // 1. GroupNorm + weight conversion
    gn_stats_kernel<<<BATCH * NGRP, 256>>>(x, stats);
    wconv_kernel<<<C3 * CH / 1024, 256>>>(qkvW, projW, qkvWh, projWh);
    gn_apply_kernel<<<dim3(NSP / 32, CH / 32, BATCH), dim3(32, 8)>>>(x, stats, gw, gb, seqh);

    // 2. QKV projection -> half
    hgemm<0><<<dim3(C3 / 128, (BATCH * NSP) / 128, 1), 128, HG_SMEM>>>(
        seqh, CH, 0, qkvWh, CH, 0, qkvh, C3, 0, CH, 1.f, qkvB, nullptr);

    // 3. V transpose
    vtrans_kernel<<<dim3(NSP / 32, CH / 32, BATCH), dim3(32, 8)>>>(qkvh, vth);

    // 4. Scores: Q K^T * scale -> fp32
    const float scale = 0.044194173824159216f;
    hgemm<1><<<dim3(NSP / 128, NSP / 128, BATCH), 128, HG_SMEM>>>(
        qkvh, C3, (long long)NSP * C3,
        qkvh + CH, C3, (long long)NSP * C3,
        scor, NSP, (long long)NSP * NSP,
        CH, scale, nullptr, nullptr);

    // 5. Softmax -> half P
    softmax_kernel<<<BATCH * NSP, 256>>>(scor, ph);

    // 6. O = P V^T -> half
    hgemm<0><<<dim3(CH / 128, NSP / 128, BATCH), 128, HG_SMEM>>>(
        ph, NSP, (long long)NSP * NSP,
        vth, NSP, (long long)CH * NSP,
        attnh, CH, (long long)NSP * CH,
        NSP, 1.f, nullptr, nullptr);

    // 7. Output projection + residual + transpose, fused -> out [b, c, h, w, d]
    hgemm<2><<<dim3(CH / 128, (BATCH * NSP) / 128, 1), 128, HG_SMEM>>>(
        attnh, CH, 0, projWh, CH, 0, out, CH, (long long)CH * NSP, CH, 1.f, projB, x);
}

// round 15
// speedup vs baseline: 1.0532x; 1.0049x over previous
#include <cuda_runtime.h>
#include <cuda_fp16.h>
#include <math.h>
#include <stdint.h>

// Problem constants
#define BATCH 2
#define CH    512
#define NSP   4096
#define C3    1536
#define NGRP  32
#define GSIZE (16*NSP)

// ---------------- scratch ----------------
__device__ __half g_seqh [(size_t)BATCH * NSP * CH];
__device__ __half g_qkvh [(size_t)BATCH * NSP * C3];
__device__ __half g_ph   [(size_t)BATCH * NSP * NSP];
__device__ __half g_vth  [(size_t)BATCH * CH * NSP];
__device__ __half g_attnh[(size_t)BATCH * NSP * CH];
__device__ __half g_qkvWh[(size_t)C3 * CH];
__device__ __half g_projWh[(size_t)CH * CH];
__device__ float  g_scor [(size_t)BATCH * NSP * NSP];
__device__ float  g_stats[BATCH * NGRP * 2];

// ---------------- helpers ----------------
__inline__ __device__ float warpSum(float v) {
    #pragma unroll
    for (int o = 16; o > 0; o >>= 1) v += __shfl_xor_sync(0xffffffffu, v, o);
    return v;
}
__inline__ __device__ float warpMax(float v) {
    #pragma unroll
    for (int o = 16; o > 0; o >>= 1) v = fmaxf(v, __shfl_xor_sync(0xffffffffu, v, o));
    return v;
}
__device__ __forceinline__ uint32_t smem_u32(const void* p) {
    uint32_t a;
    asm("{ .reg .u64 t; cvta.to.shared.u64 t, %1; cvt.u32.u64 %0, t; }" : "=r"(a) : "l"(p));
    return a;
}

// ---------------- GroupNorm stats ----------------
__global__ void gn_stats_kernel(const float* __restrict__ x, float* __restrict__ stats) {
    int bg = blockIdx.x;
    const float* p = x + (size_t)bg * GSIZE;
    float s = 0.f, ss = 0.f;
    for (int i = threadIdx.x; i < GSIZE; i += 256) {
        float v = p[i];
        s += v; ss += v * v;
    }
    s = warpSum(s); ss = warpSum(ss);
    __shared__ float shs[8], shss[8];
    int w = threadIdx.x >> 5, l = threadIdx.x & 31;
    if (l == 0) { shs[w] = s; shss[w] = ss; }
    __syncthreads();
    if (threadIdx.x == 0) {
        float S = 0.f, SS = 0.f;
        #pragma unroll
        for (int i = 0; i < 8; i++) { S += shs[i]; SS += shss[i]; }
        float mean = S * (1.f / GSIZE);
        float var  = SS * (1.f / GSIZE) - mean * mean;
        stats[2 * bg]     = mean;
        stats[2 * bg + 1] = rsqrtf(var + 1e-6f);
    }
}

// ---------------- GroupNorm apply + transpose -> half [b, n, c] ----------------
__global__ void gn_apply_kernel(const float* __restrict__ x,
                                const float* __restrict__ stats,
                                const float* __restrict__ gw,
                                const float* __restrict__ gb,
                                __half* __restrict__ seq) {
    __shared__ float t[32][33];
    int n0 = blockIdx.x * 32, c0 = blockIdx.y * 32, b = blockIdx.z;
    int tx = threadIdx.x, ty = threadIdx.y;
    #pragma unroll
    for (int j = 0; j < 4; j++) {
        int c = c0 + ty + j * 8;
        int bg = b * NGRP + (c >> 4);
        float mean = stats[2 * bg], rstd = stats[2 * bg + 1];
        float wv = gw[c] * rstd;
        float bv = gb[c] - mean * wv;
        float v = x[((size_t)(b * CH + c)) * NSP + n0 + tx];
        t[ty + j * 8][tx] = v * wv + bv;
    }
    __syncthreads();
    #pragma unroll
    for (int j = 0; j < 4; j++) {
        int n = n0 + ty + j * 8;
        seq[((size_t)(b * NSP + n)) * CH + c0 + tx] = __float2half(t[tx][ty + j * 8]);
    }
}

// ---------------- weight conversion fp32 -> fp16 ----------------
__global__ void wconv_kernel(const float* __restrict__ qkvW, const float* __restrict__ projW,
                             __half* __restrict__ qkvWh, __half* __restrict__ projWh) {
    int i = blockIdx.x * 256 + threadIdx.x;
    #pragma unroll
    for (int r = 0; r < 4; r++) {
        int idx = i * 4 + r;
        if (idx < C3 * CH) qkvWh[idx] = __float2half(qkvW[idx]);
        if (idx < CH * CH) projWh[idx] = __float2half(projW[idx]);
    }
}

// ---------------- V transpose ----------------
__global__ void vtrans_kernel(const __half* __restrict__ qkv, __half* __restrict__ vt) {
    __shared__ __half t[32][33];
    int n0 = blockIdx.x * 32, c0 = blockIdx.y * 32, b = blockIdx.z;
    int tx = threadIdx.x, ty = threadIdx.y;
    #pragma unroll
    for (int j = 0; j < 4; j++) {
        int n = n0 + ty + j * 8;
        t[ty + j * 8][tx] = qkv[((size_t)(b * NSP + n)) * C3 + 2 * CH + c0 + tx];
    }
    __syncthreads();
    #pragma unroll
    for (int j = 0; j < 4; j++) {
        int c = c0 + ty + j * 8;
        vt[((size_t)(b * CH + c)) * NSP + n0 + tx] = t[tx][ty + j * 8];
    }
}

// ---------------- fp16 NT GEMM: mma.sync m16n8k16 + ldmatrix -------------------
// BM=BN=128, BK=32; 128 threads = 4 warps (2m x 2n), warp tile 64x64.
// Fragments for BOTH kk-steps loaded up front (16 LDSM), then 64 HMMA.
// MODE: 0 = half out, 1 = float out, 2 = float out transposed + residual add.
// 4-stage cp.async ring; smem row stride 40 halfs (80B) conflict-free.
#define HROW 40
#define STAGE_B 20480         // A: 128*80 + B: 128*80
#define NSTAGE 4
#define HG_SMEM (NSTAGE * STAGE_B)   // 81920 -> 2 CTAs = 163840 <= 227KB

__device__ __forceinline__ void hfill(const __half* __restrict__ A,
                                      const __half* __restrict__ B,
                                      int lda, int ldb, int k0,
                                      uint32_t sbase, int stage, int tid) {
    uint32_t sa = sbase + stage * STAGE_B;
    uint32_t sb = sa + 10240;
    #pragma unroll
    for (int i = 0; i < 4; i++) {
        int idx = tid + 128 * i;
        int row = idx >> 2, c = idx & 3;
        const __half* g = A + (long long)row * lda + k0 + c * 8;
        asm volatile("cp.async.cg.shared.global [%0], [%1], 16;"
                     :: "r"(sa + row * 80 + c * 16), "l"(g));
    }
    #pragma unroll
    for (int i = 0; i < 4; i++) {
        int idx = tid + 128 * i;
        int row = idx >> 2, c = idx & 3;
        const __half* g = B + (long long)row * ldb + k0 + c * 8;
        asm volatile("cp.async.cg.shared.global [%0], [%1], 16;"
                     :: "r"(sb + row * 80 + c * 16), "l"(g));
    }
    asm volatile("cp.async.commit_group;" ::: "memory");
}

template <int MODE>
__global__ void __launch_bounds__(128, 2) hgemm(
    const __half* __restrict__ A, int lda, long long sA,
    const __half* __restrict__ B, int ldb, long long sB,
    void* __restrict__ Cv, int ldc, long long sC,
    int K, float alpha, const float* __restrict__ bias,
    const float* __restrict__ xres) {

    extern __shared__ char smem[];
    uint32_t sbase = smem_u32(smem);

    const int tid = threadIdx.x;
    const int lane = tid & 31;
    const int wid = tid >> 5;
    const int warpM = wid >> 1;          // 0..1
    const int warpN = wid & 1;           // 0..1
    const int g = lane >> 2, t4 = lane & 3;
    const int l8 = lane & 7, lm = lane >> 3;

    A += blockIdx.z * sA + (long long)blockIdx.y * 128 * lda;
    B += blockIdx.z * sB + (long long)blockIdx.x * 128 * ldb;

    const uint32_t a_off = (uint32_t)(((lm & 1) * 8 + l8) * 80 + (lm >> 1) * 16)
                         + (uint32_t)(warpM * 64) * 80;
    const uint32_t b_off = (uint32_t)(((lm >> 1) * 8 + l8) * 80 + (lm & 1) * 16)
                         + (uint32_t)(warpN * 64) * 80;

    float acc[4][8][4];
    #pragma unroll
    for (int i = 0; i < 4; i++)
        #pragma unroll
        for (int j = 0; j < 8; j++)
            #pragma unroll
            for (int q = 0; q < 4; q++) acc[i][j][q] = 0.f;

    const int S = K / 32;

    // prologue: 3 groups in flight
    #pragma unroll
    for (int s = 0; s < 3; s++)
        hfill(A, B, lda, ldb, s * 32, sbase, s, tid);

    int stage = 0;
    #pragma unroll 1
    for (int s = 0; s < S; s++) {
        const int rem = S - 1 - s;
        if (rem >= 2)      asm volatile("cp.async.wait_group 2;" ::: "memory");
        else if (rem == 1) asm volatile("cp.async.wait_group 1;" ::: "memory");
        else               asm volatile("cp.async.wait_group 0;" ::: "memory");
        __syncthreads();
        if (s + 3 < S) {
            int fstage = stage + 3; if (fstage >= NSTAGE) fstage -= NSTAGE;
            hfill(A, B, lda, ldb, (s + 3) * 32, sbase, fstage, tid);
        }

        const uint32_t sAb = sbase + stage * STAGE_B;
        const uint32_t sBb = sAb + 10240;

        // Load ALL fragments for both kk-steps first (16 LDSM), then 64 HMMA.
        uint32_t af[2][4][4];
        uint32_t bf[2][8][2];
        #pragma unroll
        for (int kk = 0; kk < 2; kk++) {
            const uint32_t kadd = kk * 32;
            #pragma unroll
            for (int mf = 0; mf < 4; mf++) {
                asm volatile("ldmatrix.sync.aligned.m8n8.x4.shared.b16 {%0,%1,%2,%3}, [%4];"
                    : "=r"(af[kk][mf][0]), "=r"(af[kk][mf][1]),
                      "=r"(af[kk][mf][2]), "=r"(af[kk][mf][3])
                    : "r"(sAb + a_off + mf * 1280 + kadd));
            }
            #pragma unroll
            for (int p = 0; p < 4; p++) {
                asm volatile("ldmatrix.sync.aligned.m8n8.x4.shared.b16 {%0,%1,%2,%3}, [%4];"
                    : "=r"(bf[kk][2*p][0]), "=r"(bf[kk][2*p][1]),
                      "=r"(bf[kk][2*p+1][0]), "=r"(bf[kk][2*p+1][1])
                    : "r"(sBb + b_off + p * 1280 + kadd));
            }
        }
        #pragma unroll
        for (int kk = 0; kk < 2; kk++)
            #pragma unroll
            for (int mf = 0; mf < 4; mf++)
                #pragma unroll
                for (int nf = 0; nf < 8; nf++) {
                    asm volatile(
                        "mma.sync.aligned.m16n8k16.row.col.f32.f16.f16.f32 "
                        "{%0,%1,%2,%3}, {%4,%5,%6,%7}, {%8,%9}, {%0,%1,%2,%3};"
                        : "+f"(acc[mf][nf][0]), "+f"(acc[mf][nf][1]),
                          "+f"(acc[mf][nf][2]), "+f"(acc[mf][nf][3])
                        : "r"(af[kk][mf][0]), "r"(af[kk][mf][1]),
                          "r"(af[kk][mf][2]), "r"(af[kk][mf][3]),
                          "r"(bf[kk][nf][0]), "r"(bf[kk][nf][1]));
                }
        if (++stage >= NSTAGE) stage = 0;
    }

    const float* bp = bias ? bias + blockIdx.x * 128 : nullptr;
    #pragma unroll
    for (int mf = 0; mf < 4; mf++) {
        const int row = warpM * 64 + mf * 16 + g;
        #pragma unroll
        for (int nf = 0; nf < 8; nf++) {
            const int col = warpN * 64 + nf * 8 + 2 * t4;
            float b0 = 0.f, b1 = 0.f;
            if (bp) { b0 = bp[col]; b1 = bp[col + 1]; }
            float v00 = alpha * acc[mf][nf][0] + b0;
            float v01 = alpha * acc[mf][nf][1] + b1;
            float v10 = alpha * acc[mf][nf][2] + b0;
            float v11 = alpha * acc[mf][nf][3] + b1;
            if (MODE == 0) {
                __half* C = (__half*)Cv + blockIdx.z * sC
                          + (long long)blockIdx.y * 128 * ldc + blockIdx.x * 128;
                *(__half2*)(C + (long long)row * ldc + col)       = __floats2half2_rn(v00, v01);
                *(__half2*)(C + (long long)(row + 8) * ldc + col) = __floats2half2_rn(v10, v11);
            } else if (MODE == 1) {
                float* C = (float*)Cv + blockIdx.z * sC
                         + (long long)blockIdx.y * 128 * ldc + blockIdx.x * 128;
                float2 u0 = { v00, v01 }, u1 = { v10, v11 };
                *(float2*)(C + (long long)row * ldc + col)       = u0;
                *(float2*)(C + (long long)(row + 8) * ldc + col) = u1;
            } else {
                // MODE 2: transposed residual write: out[b, c, n] = x[b, c, n] + v
                const int rowg = blockIdx.y * 128 + row;
                const int b  = rowg >> 12;        // / NSP
                const int n  = rowg & (NSP - 1);
                const int c0 = blockIdx.x * 128 + col;
                float* out = (float*)Cv;
                size_t base = (size_t)b * CH * NSP + n;
                size_t i00 = base + (size_t)c0 * NSP;
                size_t i01 = base + (size_t)(c0 + 1) * NSP;
                out[i00]     = xres[i00]     + v00;
                out[i01]     = xres[i01]     + v01;
                out[i00 + 8] = xres[i00 + 8] + v10;
                out[i01 + 8] = xres[i01 + 8] + v11;
            }
        }
    }
}

// ---------------- row softmax fp32 -> half P ----------------
__global__ void __launch_bounds__(256) softmax_kernel(const float* __restrict__ S,
                                                      __half* __restrict__ P) {
    const float* p = S + (size_t)blockIdx.x * NSP;
    __half2* o = (__half2*)(P + (size_t)blockIdx.x * NSP);
    float4 v[4];
    const int t = threadIdx.x;
    float m = -1e30f;
    #pragma unroll
    for (int i = 0; i < 4; i++) {
        v[i] = ((const float4*)p)[t + 256 * i];
        m = fmaxf(m, fmaxf(fmaxf(v[i].x, v[i].y), fmaxf(v[i].z, v[i].w)));
    }
    __shared__ float red[8];
    int w = t >> 5, l = t & 31;
    m = warpMax(m);
    if (l == 0) red[w] = m;
    __syncthreads();
    if (w == 0) {
        float tm = (l < 8) ? red[l] : -1e30f;
        tm = warpMax(tm);
        if (l == 0) red[0] = tm;
    }
    __syncthreads();
    m = red[0];
    __syncthreads();

    float s = 0.f;
    #pragma unroll
    for (int i = 0; i < 4; i++) {
        v[i].x = __expf(v[i].x - m);
        v[i].y = __expf(v[i].y - m);
        v[i].z = __expf(v[i].z - m);
        v[i].w = __expf(v[i].w - m);
        s += v[i].x + v[i].y + v[i].z + v[i].w;
    }
    s = warpSum(s);
    if (l == 0) red[w] = s;
    __syncthreads();
    if (w == 0) {
        float ts = (l < 8) ? red[l] : 0.f;
        ts = warpSum(ts);
        if (l == 0) red[0] = ts;
    }
    __syncthreads();
    float inv = __frcp_rn(red[0]);
    #pragma unroll
    for (int i = 0; i < 4; i++) {
        int base = (t + 256 * i) * 2;
        o[base]     = __floats2half2_rn(v[i].x * inv, v[i].y * inv);
        o[base + 1] = __floats2half2_rn(v[i].z * inv, v[i].w * inv);
    }
}

// ---------------- launch ----------------
extern "C" void kernel_launch(void* const* d_in, const int* in_sizes, int n_in,
                              void* d_out, int out_size) {
    const float* x     = (const float*)d_in[0];
    const float* gw    = (const float*)d_in[1];
    const float* gb    = (const float*)d_in[2];
    const float* qkvW  = (const float*)d_in[3];
    const float* qkvB  = (const float*)d_in[4];
    const float* projW = (const float*)d_in[5];
    const float* projB = (const float*)d_in[6];
    float* out = (float*)d_out;

    __half *seqh, *qkvh, *ph, *vth, *attnh, *qkvWh, *projWh;
    float *scor, *stats;
    cudaGetSymbolAddress((void**)&seqh,  g_seqh);
    cudaGetSymbolAddress((void**)&qkvh,  g_qkvh);
    cudaGetSymbolAddress((void**)&ph,    g_ph);
    cudaGetSymbolAddress((void**)&vth,   g_vth);
    cudaGetSymbolAddress((void**)&attnh, g_attnh);
    cudaGetSymbolAddress((void**)&qkvWh, g_qkvWh);
    cudaGetSymbolAddress((void**)&projWh,g_projWh);
    cudaGetSymbolAddress((void**)&scor,  g_scor);
    cudaGetSymbolAddress((void**)&stats, g_stats);

    static bool attr_done = false;
    if (!attr_done) {
        cudaFuncSetAttribute((const void*)hgemm<0>,
                             cudaFuncAttributeMaxDynamicSharedMemorySize, HG_SMEM);
        cudaFuncSetAttribute((const void*)hgemm<1>,
                             cudaFuncAttributeMaxDynamicSharedMemorySize, HG_SMEM);
        cudaFuncSetAttribute((const void*)hgemm<2>,
                             cudaFuncAttributeMaxDynamicSharedMemorySize, HG_SMEM);
        attr_done = true;
    }

    // 1. GroupNorm + weight conversion
    gn_stats_kernel<<<BATCH * NGRP, 256>>>(x, stats);
    wconv_kernel<<<C3 * CH / 1024, 256>>>(qkvW, projW, qkvWh, projWh);
    gn_apply_kernel<<<dim3(NSP / 32, CH / 32, BATCH), dim3(32, 8)>>>(x, stats, gw, gb, seqh);

    // 2. QKV projection -> half
    hgemm<0><<<dim3(C3 / 128, (BATCH * NSP) / 128, 1), 128, HG_SMEM>>>(
        seqh, CH, 0, qkvWh, CH, 0, qkvh, C3, 0, CH, 1.f, qkvB, nullptr);

    // 3. V transpose
    vtrans_kernel<<<dim3(NSP / 32, CH / 32, BATCH), dim3(32, 8)>>>(qkvh, vth);

    // 4. Scores: Q K^T * scale -> fp32
    const float scale = 0.044194173824159216f;
    hgemm<1><<<dim3(NSP / 128, NSP / 128, BATCH), 128, HG_SMEM>>>(
        qkvh, C3, (long long)NSP * C3,
        qkvh + CH, C3, (long long)NSP * C3,
        scor, NSP, (long long)NSP * NSP,
        CH, scale, nullptr, nullptr);

    // 5. Softmax -> half P
    softmax_kernel<<<BATCH * NSP, 256>>>(scor, ph);

    // 6. O = P V^T -> half
    hgemm<0><<<dim3(CH / 128, NSP / 128, BATCH), 128, HG_SMEM>>>(
        ph, NSP, (long long)NSP * NSP,
        vth, NSP, (long long)CH * NSP,
        attnh, CH, (long long)NSP * CH,
        NSP, 1.f, nullptr, nullptr);

    // 7. Output projection + residual + transpose, fused -> out [b, c, h, w, d]
    hgemm<2><<<dim3(CH / 128, (BATCH * NSP) / 128, 1), 128, HG_SMEM>>>(
        attnh, CH, 0, projWh, CH, 0, out, CH, (long long)CH * NSP, CH, 1.f, projB, x);
}

// round 16
// speedup vs baseline: 1.1293x; 1.0723x over previous
#include <cuda_runtime.h>
#include <cuda_fp16.h>
#include <math.h>
#include <stdint.h>

// Problem constants
#define BATCH 2
#define CH    512
#define NSP   4096
#define C3    1536
#define NGRP  32
#define GSIZE (16*NSP)

// ---------------- scratch ----------------
__device__ __half g_seqh [(size_t)BATCH * NSP * CH];
__device__ __half g_qkvh [(size_t)BATCH * NSP * C3];
__device__ __half g_ph   [(size_t)BATCH * NSP * NSP];
__device__ __half g_vth  [(size_t)BATCH * CH * NSP];
__device__ __half g_attnh[(size_t)BATCH * NSP * CH];
__device__ __half g_qkvWh[(size_t)C3 * CH];
__device__ __half g_projWh[(size_t)CH * CH];
__device__ float  g_rowsum[(size_t)BATCH * NSP];
__device__ float  g_stats[BATCH * NGRP * 2];

// ---------------- helpers ----------------
__inline__ __device__ float warpSum(float v) {
    #pragma unroll
    for (int o = 16; o > 0; o >>= 1) v += __shfl_xor_sync(0xffffffffu, v, o);
    return v;
}
__device__ __forceinline__ uint32_t smem_u32(const void* p) {
    uint32_t a;
    asm("{ .reg .u64 t; cvta.to.shared.u64 t, %1; cvt.u32.u64 %0, t; }" : "=r"(a) : "l"(p));
    return a;
}

// ---------------- GroupNorm stats ----------------
__global__ void gn_stats_kernel(const float* __restrict__ x, float* __restrict__ stats) {
    int bg = blockIdx.x;
    const float* p = x + (size_t)bg * GSIZE;
    float s = 0.f, ss = 0.f;
    for (int i = threadIdx.x; i < GSIZE; i += 256) {
        float v = p[i];
        s += v; ss += v * v;
    }
    s = warpSum(s); ss = warpSum(ss);
    __shared__ float shs[8], shss[8];
    int w = threadIdx.x >> 5, l = threadIdx.x & 31;
    if (l == 0) { shs[w] = s; shss[w] = ss; }
    __syncthreads();
    if (threadIdx.x == 0) {
        float S = 0.f, SS = 0.f;
        #pragma unroll
        for (int i = 0; i < 8; i++) { S += shs[i]; SS += shss[i]; }
        float mean = S * (1.f / GSIZE);
        float var  = SS * (1.f / GSIZE) - mean * mean;
        stats[2 * bg]     = mean;
        stats[2 * bg + 1] = rsqrtf(var + 1e-6f);
    }
}

// ---------------- zero rowsum ----------------
__global__ void zero_kernel(float* __restrict__ p) {
    p[blockIdx.x * 1024 + threadIdx.x] = 0.f;
}

// ---------------- GroupNorm apply + transpose -> half [b, n, c] ----------------
__global__ void gn_apply_kernel(const float* __restrict__ x,
                                const float* __restrict__ stats,
                                const float* __restrict__ gw,
                                const float* __restrict__ gb,
                                __half* __restrict__ seq) {
    __shared__ float t[32][33];
    int n0 = blockIdx.x * 32, c0 = blockIdx.y * 32, b = blockIdx.z;
    int tx = threadIdx.x, ty = threadIdx.y;
    #pragma unroll
    for (int j = 0; j < 4; j++) {
        int c = c0 + ty + j * 8;
        int bg = b * NGRP + (c >> 4);
        float mean = stats[2 * bg], rstd = stats[2 * bg + 1];
        float wv = gw[c] * rstd;
        float bv = gb[c] - mean * wv;
        float v = x[((size_t)(b * CH + c)) * NSP + n0 + tx];
        t[ty + j * 8][tx] = v * wv + bv;
    }
    __syncthreads();
    #pragma unroll
    for (int j = 0; j < 4; j++) {
        int n = n0 + ty + j * 8;
        seq[((size_t)(b * NSP + n)) * CH + c0 + tx] = __float2half(t[tx][ty + j * 8]);
    }
}

// ---------------- weight conversion fp32 -> fp16 ----------------
__global__ void wconv_kernel(const float* __restrict__ qkvW, const float* __restrict__ projW,
                             __half* __restrict__ qkvWh, __half* __restrict__ projWh) {
    int i = blockIdx.x * 256 + threadIdx.x;
    #pragma unroll
    for (int r = 0; r < 4; r++) {
        int idx = i * 4 + r;
        if (idx < C3 * CH) qkvWh[idx] = __float2half(qkvW[idx]);
        if (idx < CH * CH) projWh[idx] = __float2half(projW[idx]);
    }
}

// ---------------- V transpose ----------------
__global__ void vtrans_kernel(const __half* __restrict__ qkv, __half* __restrict__ vt) {
    __shared__ __half t[32][33];
    int n0 = blockIdx.x * 32, c0 = blockIdx.y * 32, b = blockIdx.z;
    int tx = threadIdx.x, ty = threadIdx.y;
    #pragma unroll
    for (int j = 0; j < 4; j++) {
        int n = n0 + ty + j * 8;
        t[ty + j * 8][tx] = qkv[((size_t)(b * NSP + n)) * C3 + 2 * CH + c0 + tx];
    }
    __syncthreads();
    #pragma unroll
    for (int j = 0; j < 4; j++) {
        int c = c0 + ty + j * 8;
        vt[((size_t)(b * CH + c)) * NSP + n0 + tx] = t[tx][ty + j * 8];
    }
}

// ---------------- fp16 NT GEMM: mma.sync m16n8k16 + ldmatrix -------------------
// BM=BN=128, BK=32; 128 threads = 4 warps (2m x 2n), warp tile 64x64.
// MODE: 0 = half out
//       2 = float out transposed + residual add (aux = x residual, fp32)
//       3 = p = exp(alpha*acc) half out + row-sum atomicAdd into aux
//       4 = half out scaled by 1/aux[row]  (softmax normalization)
// 4-stage cp.async ring; smem row stride 40 halfs (80B) conflict-free.
#define HROW 40
#define STAGE_B 20480
#define NSTAGE 4
#define HG_SMEM (NSTAGE * STAGE_B)   // 81920 -> 2 CTAs = 163840

__device__ __forceinline__ void hfill(const __half* __restrict__ A,
                                      const __half* __restrict__ B,
                                      int lda, int ldb, int k0,
                                      uint32_t sbase, int stage, int tid) {
    uint32_t sa = sbase + stage * STAGE_B;
    uint32_t sb = sa + 10240;
    #pragma unroll
    for (int i = 0; i < 4; i++) {
        int idx = tid + 128 * i;
        int row = idx >> 2, c = idx & 3;
        const __half* g = A + (long long)row * lda + k0 + c * 8;
        asm volatile("cp.async.cg.shared.global [%0], [%1], 16;"
                     :: "r"(sa + row * 80 + c * 16), "l"(g));
    }
    #pragma unroll
    for (int i = 0; i < 4; i++) {
        int idx = tid + 128 * i;
        int row = idx >> 2, c = idx & 3;
        const __half* g = B + (long long)row * ldb + k0 + c * 8;
        asm volatile("cp.async.cg.shared.global [%0], [%1], 16;"
                     :: "r"(sb + row * 80 + c * 16), "l"(g));
    }
    asm volatile("cp.async.commit_group;" ::: "memory");
}

template <int MODE>
__global__ void __launch_bounds__(128, 2) hgemm(
    const __half* __restrict__ A, int lda, long long sA,
    const __half* __restrict__ B, int ldb, long long sB,
    void* __restrict__ Cv, int ldc, long long sC,
    int K, float alpha, const float* __restrict__ bias,
    float* __restrict__ aux) {

    extern __shared__ char smem[];
    uint32_t sbase = smem_u32(smem);

    const int tid = threadIdx.x;
    const int lane = tid & 31;
    const int wid = tid >> 5;
    const int warpM = wid >> 1;
    const int warpN = wid & 1;
    const int g = lane >> 2, t4 = lane & 3;
    const int l8 = lane & 7, lm = lane >> 3;

    A += blockIdx.z * sA + (long long)blockIdx.y * 128 * lda;
    B += blockIdx.z * sB + (long long)blockIdx.x * 128 * ldb;

    const uint32_t a_off = (uint32_t)(((lm & 1) * 8 + l8) * 80 + (lm >> 1) * 16)
                         + (uint32_t)(warpM * 64) * 80;
    const uint32_t b_off = (uint32_t)(((lm >> 1) * 8 + l8) * 80 + (lm & 1) * 16)
                         + (uint32_t)(warpN * 64) * 80;

    float acc[4][8][4];
    #pragma unroll
    for (int i = 0; i < 4; i++)
        #pragma unroll
        for (int j = 0; j < 8; j++)
            #pragma unroll
            for (int q = 0; q < 4; q++) acc[i][j][q] = 0.f;

    const int S = K / 32;

    #pragma unroll
    for (int s = 0; s < 3; s++)
        hfill(A, B, lda, ldb, s * 32, sbase, s, tid);

    int stage = 0;
    #pragma unroll 1
    for (int s = 0; s < S; s++) {
        const int rem = S - 1 - s;
        if (rem >= 2)      asm volatile("cp.async.wait_group 2;" ::: "memory");
        else if (rem == 1) asm volatile("cp.async.wait_group 1;" ::: "memory");
        else               asm volatile("cp.async.wait_group 0;" ::: "memory");
        __syncthreads();
        if (s + 3 < S) {
            int fstage = stage + 3; if (fstage >= NSTAGE) fstage -= NSTAGE;
            hfill(A, B, lda, ldb, (s + 3) * 32, sbase, fstage, tid);
        }

        const uint32_t sAb = sbase + stage * STAGE_B;
        const uint32_t sBb = sAb + 10240;

        #pragma unroll
        for (int kk = 0; kk < 2; kk++) {
            const uint32_t kadd = kk * 32;
            uint32_t af[4][4];
            #pragma unroll
            for (int mf = 0; mf < 4; mf++) {
                asm volatile("ldmatrix.sync.aligned.m8n8.x4.shared.b16 {%0,%1,%2,%3}, [%4];"
                    : "=r"(af[mf][0]), "=r"(af[mf][1]), "=r"(af[mf][2]), "=r"(af[mf][3])
                    : "r"(sAb + a_off + mf * 1280 + kadd));
            }
            uint32_t bf[8][2];
            #pragma unroll
            for (int p = 0; p < 4; p++) {
                asm volatile("ldmatrix.sync.aligned.m8n8.x4.shared.b16 {%0,%1,%2,%3}, [%4];"
                    : "=r"(bf[2*p][0]), "=r"(bf[2*p][1]), "=r"(bf[2*p+1][0]), "=r"(bf[2*p+1][1])
                    : "r"(sBb + b_off + p * 1280 + kadd));
            }
            #pragma unroll
            for (int mf = 0; mf < 4; mf++)
                #pragma unroll
                for (int nf = 0; nf < 8; nf++) {
                    asm volatile(
                        "mma.sync.aligned.m16n8k16.row.col.f32.f16.f16.f32 "
                        "{%0,%1,%2,%3}, {%4,%5,%6,%7}, {%8,%9}, {%0,%1,%2,%3};"
                        : "+f"(acc[mf][nf][0]), "+f"(acc[mf][nf][1]),
                          "+f"(acc[mf][nf][2]), "+f"(acc[mf][nf][3])
                        : "r"(af[mf][0]), "r"(af[mf][1]), "r"(af[mf][2]), "r"(af[mf][3]),
                          "r"(bf[nf][0]), "r"(bf[nf][1]));
                }
        }
        if (++stage >= NSTAGE) stage = 0;
    }

    const float* bp = bias ? bias + blockIdx.x * 128 : nullptr;
    #pragma unroll
    for (int mf = 0; mf < 4; mf++) {
        const int row = warpM * 64 + mf * 16 + g;
        float r0 = 0.f, r1 = 0.f;     // MODE 3: partial row sums
        float inv0 = 1.f, inv1 = 1.f; // MODE 4: normalization
        if (MODE == 4) {
            const float* rs = aux + (size_t)blockIdx.z * NSP + blockIdx.y * 128;
            inv0 = 1.f / rs[row];
            inv1 = 1.f / rs[row + 8];
        }
        #pragma unroll
        for (int nf = 0; nf < 8; nf++) {
            const int col = warpN * 64 + nf * 8 + 2 * t4;
            float b0 = 0.f, b1 = 0.f;
            if (bp) { b0 = bp[col]; b1 = bp[col + 1]; }
            float v00 = alpha * acc[mf][nf][0] + b0;
            float v01 = alpha * acc[mf][nf][1] + b1;
            float v10 = alpha * acc[mf][nf][2] + b0;
            float v11 = alpha * acc[mf][nf][3] + b1;
            if (MODE == 0 || MODE == 4) {
                if (MODE == 4) { v00 *= inv0; v01 *= inv0; v10 *= inv1; v11 *= inv1; }
                __half* C = (__half*)Cv + blockIdx.z * sC
                          + (long long)blockIdx.y * 128 * ldc + blockIdx.x * 128;
                *(__half2*)(C + (long long)row * ldc + col)       = __floats2half2_rn(v00, v01);
                *(__half2*)(C + (long long)(row + 8) * ldc + col) = __floats2half2_rn(v10, v11);
            } else if (MODE == 3) {
                float e00 = __expf(v00), e01 = __expf(v01);
                float e10 = __expf(v10), e11 = __expf(v11);
                __half* C = (__half*)Cv + blockIdx.z * sC
                          + (long long)blockIdx.y * 128 * ldc + blockIdx.x * 128;
                *(__half2*)(C + (long long)row * ldc + col)       = __floats2half2_rn(e00, e01);
                *(__half2*)(C + (long long)(row + 8) * ldc + col) = __floats2half2_rn(e10, e11);
                r0 += e00 + e01;
                r1 += e10 + e11;
            } else {
                // MODE 2: transposed residual write: out[b, c, n] = x[b, c, n] + v
                const int rowg = blockIdx.y * 128 + row;
                const int b  = rowg >> 12;
                const int n  = rowg & (NSP - 1);
                const int c0 = blockIdx.x * 128 + col;
                float* out = (float*)Cv;
                const float* xres = aux;
                size_t base = (size_t)b * CH * NSP + n;
                size_t i00 = base + (size_t)c0 * NSP;
                size_t i01 = base + (size_t)(c0 + 1) * NSP;
                out[i00]     = xres[i00]     + v00;
                out[i01]     = xres[i01]     + v01;
                out[i00 + 8] = xres[i00 + 8] + v10;
                out[i01 + 8] = xres[i01 + 8] + v11;
            }
        }
        if (MODE == 3) {
            // reduce partial sums across the t4 quad (lanes g*4 + t4)
            r0 += __shfl_xor_sync(0xffffffffu, r0, 1);
            r0 += __shfl_xor_sync(0xffffffffu, r0, 2);
            r1 += __shfl_xor_sync(0xffffffffu, r1, 1);
            r1 += __shfl_xor_sync(0xffffffffu, r1, 2);
            if (t4 == 0) {
                float* rs = aux + (size_t)blockIdx.z * NSP + blockIdx.y * 128;
                atomicAdd(rs + row, r0);
                atomicAdd(rs + row + 8, r1);
            }
        }
    }
}

// ---------------- launch ----------------
extern "C" void kernel_launch(void* const* d_in, const int* in_sizes, int n_in,
                              void* d_out, int out_size) {
    const float* x     = (const float*)d_in[0];
    const float* gw    = (const float*)d_in[1];
    const float* gb    = (const float*)d_in[2];
    const float* qkvW  = (const float*)d_in[3];
    const float* qkvB  = (const float*)d_in[4];
    const float* projW = (const float*)d_in[5];
    const float* projB = (const float*)d_in[6];
    float* out = (float*)d_out;

    __half *seqh, *qkvh, *ph, *vth, *attnh, *qkvWh, *projWh;
    float *rowsum, *stats;
    cudaGetSymbolAddress((void**)&seqh,  g_seqh);
    cudaGetSymbolAddress((void**)&qkvh,  g_qkvh);
    cudaGetSymbolAddress((void**)&ph,    g_ph);
    cudaGetSymbolAddress((void**)&vth,   g_vth);
    cudaGetSymbolAddress((void**)&attnh, g_attnh);
    cudaGetSymbolAddress((void**)&qkvWh, g_qkvWh);
    cudaGetSymbolAddress((void**)&projWh,g_projWh);
    cudaGetSymbolAddress((void**)&rowsum,g_rowsum);
    cudaGetSymbolAddress((void**)&stats, g_stats);

    static bool attr_done = false;
    if (!attr_done) {
        cudaFuncSetAttribute((const void*)hgemm<0>,
                             cudaFuncAttributeMaxDynamicSharedMemorySize, HG_SMEM);
        cudaFuncSetAttribute((const void*)hgemm<2>,
                             cudaFuncAttributeMaxDynamicSharedMemorySize, HG_SMEM);
        cudaFuncSetAttribute((const void*)hgemm<3>,
                             cudaFuncAttributeMaxDynamicSharedMemorySize, HG_SMEM);
        cudaFuncSetAttribute((const void*)hgemm<4>,
                             cudaFuncAttributeMaxDynamicSharedMemorySize, HG_SMEM);
        attr_done = true;
    }

    // 1. GroupNorm + weight conversion + rowsum zero
    gn_stats_kernel<<<BATCH * NGRP, 256>>>(x, stats);
    wconv_kernel<<<C3 * CH / 1024, 256>>>(qkvW, projW, qkvWh, projWh);
    zero_kernel<<<BATCH * NSP / 1024, 1024>>>(rowsum);
    gn_apply_kernel<<<dim3(NSP / 32, CH / 32, BATCH), dim3(32, 8)>>>(x, stats, gw, gb, seqh);

    // 2. QKV projection -> half
    hgemm<0><<<dim3(C3 / 128, (BATCH * NSP) / 128, 1), 128, HG_SMEM>>>(
        seqh, CH, 0, qkvWh, CH, 0, qkvh, C3, 0, CH, 1.f, qkvB, nullptr);

    // 3. V transpose
    vtrans_kernel<<<dim3(NSP / 32, CH / 32, BATCH), dim3(32, 8)>>>(qkvh, vth);

    // 4. P = exp(Q K^T * scale) -> half, rowsum accumulated (no separate softmax)
    const float scale = 0.044194173824159216f;
    hgemm<3><<<dim3(NSP / 128, NSP / 128, BATCH), 128, HG_SMEM>>>(
        qkvh, C3, (long long)NSP * C3,
        qkvh + CH, C3, (long long)NSP * C3,
        ph, NSP, (long long)NSP * NSP,
        CH, scale, nullptr, rowsum);

    // 5. O = (P V^T) / rowsum -> half
    hgemm<4><<<dim3(CH / 128, NSP / 128, BATCH), 128, HG_SMEM>>>(
        ph, NSP, (long long)NSP * NSP,
        vth, NSP, (long long)CH * NSP,
        attnh, CH, (long long)NSP * CH,
        NSP, 1.f, nullptr, rowsum);

    // 6. Output projection + residual + transpose, fused -> out [b, c, h, w, d]
    hgemm<2><<<dim3(CH / 128, (BATCH * NSP) / 128, 1), 128, HG_SMEM>>>(
        attnh, CH, 0, projWh, CH, 0, out, CH, (long long)CH * NSP, CH, 1.f, projB, (float*)x);
}

// round 17
// speedup vs baseline: 1.1369x; 1.0067x over previous
#include <cuda_runtime.h>
#include <cuda_fp16.h>
#include <math.h>
#include <stdint.h>

// Problem constants
#define BATCH 2
#define CH    512
#define NSP   4096
#define C3    1536
#define NGRP  32
#define GSIZE (16*NSP)

// ---------------- scratch ----------------
__device__ __half g_seqh [(size_t)BATCH * NSP * CH];
__device__ __half g_qkvh [(size_t)BATCH * NSP * C3];
__device__ __half g_ph   [(size_t)BATCH * NSP * NSP];
__device__ __half g_vth  [(size_t)BATCH * CH * NSP];
__device__ __half g_attnh[(size_t)BATCH * NSP * CH];
__device__ __half g_qkvWh[(size_t)C3 * CH];
__device__ __half g_projWh[(size_t)CH * CH];
__device__ float  g_rowsum[(size_t)BATCH * NSP];
__device__ float  g_stats[BATCH * NGRP * 2];

// ---------------- helpers ----------------
__inline__ __device__ float warpSum(float v) {
    #pragma unroll
    for (int o = 16; o > 0; o >>= 1) v += __shfl_xor_sync(0xffffffffu, v, o);
    return v;
}
__device__ __forceinline__ uint32_t smem_u32(const void* p) {
    uint32_t a;
    asm("{ .reg .u64 t; cvta.to.shared.u64 t, %1; cvt.u32.u64 %0, t; }" : "=r"(a) : "l"(p));
    return a;
}

// ---------------- GroupNorm stats ----------------
__global__ void gn_stats_kernel(const float* __restrict__ x, float* __restrict__ stats) {
    int bg = blockIdx.x;
    const float* p = x + (size_t)bg * GSIZE;
    float s = 0.f, ss = 0.f;
    for (int i = threadIdx.x; i < GSIZE; i += 256) {
        float v = p[i];
        s += v; ss += v * v;
    }
    s = warpSum(s); ss = warpSum(ss);
    __shared__ float shs[8], shss[8];
    int w = threadIdx.x >> 5, l = threadIdx.x & 31;
    if (l == 0) { shs[w] = s; shss[w] = ss; }
    __syncthreads();
    if (threadIdx.x == 0) {
        float S = 0.f, SS = 0.f;
        #pragma unroll
        for (int i = 0; i < 8; i++) { S += shs[i]; SS += shss[i]; }
        float mean = S * (1.f / GSIZE);
        float var  = SS * (1.f / GSIZE) - mean * mean;
        stats[2 * bg]     = mean;
        stats[2 * bg + 1] = rsqrtf(var + 1e-6f);
    }
}

// ---------------- GroupNorm apply + transpose -> half [b, n, c] ----------------
__global__ void gn_apply_kernel(const float* __restrict__ x,
                                const float* __restrict__ stats,
                                const float* __restrict__ gw,
                                const float* __restrict__ gb,
                                __half* __restrict__ seq) {
    __shared__ float t[32][33];
    int n0 = blockIdx.x * 32, c0 = blockIdx.y * 32, b = blockIdx.z;
    int tx = threadIdx.x, ty = threadIdx.y;
    #pragma unroll
    for (int j = 0; j < 4; j++) {
        int c = c0 + ty + j * 8;
        int bg = b * NGRP + (c >> 4);
        float mean = stats[2 * bg], rstd = stats[2 * bg + 1];
        float wv = gw[c] * rstd;
        float bv = gb[c] - mean * wv;
        float v = x[((size_t)(b * CH + c)) * NSP + n0 + tx];
        t[ty + j * 8][tx] = v * wv + bv;
    }
    __syncthreads();
    #pragma unroll
    for (int j = 0; j < 4; j++) {
        int n = n0 + ty + j * 8;
        seq[((size_t)(b * NSP + n)) * CH + c0 + tx] = __float2half(t[tx][ty + j * 8]);
    }
}

// ---------------- weight conversion fp32 -> fp16 (+ rowsum zero) ----------------
__global__ void wconv_kernel(const float* __restrict__ qkvW, const float* __restrict__ projW,
                             __half* __restrict__ qkvWh, __half* __restrict__ projWh,
                             float* __restrict__ rowsum) {
    int i = blockIdx.x * 256 + threadIdx.x;
    #pragma unroll
    for (int r = 0; r < 4; r++) {
        int idx = i * 4 + r;
        if (idx < C3 * CH) qkvWh[idx] = __float2half(qkvW[idx]);
        if (idx < CH * CH) projWh[idx] = __float2half(projW[idx]);
        if (idx < BATCH * NSP) rowsum[idx] = 0.f;
    }
}

// ---------------- fp16 NT GEMM: mma.sync m16n8k16 + ldmatrix -------------------
// BM=BN=128, BK=32; 128 threads = 4 warps (2m x 2n), warp tile 64x64.
// MODE: 0 = half out
//       2 = float out transposed + residual add (aux = x residual)
//       3 = p = exp(alpha*acc) half out + row-sum atomicAdd into aux
//       4 = half out scaled by 1/aux[row]  (softmax normalization)
//       5 = QKV: Q,K tiles (bx<8) half out; V tiles (bx>=8) transposed -> vout
// 4-stage cp.async ring; smem row stride 40 halfs (80B) conflict-free.
#define HROW 40
#define STAGE_B 20480
#define NSTAGE 4
#define HG_SMEM (NSTAGE * STAGE_B)   // 81920 -> 2 CTAs = 163840

__device__ __forceinline__ void hfill(const __half* __restrict__ A,
                                      const __half* __restrict__ B,
                                      int lda, int ldb, int k0,
                                      uint32_t sbase, int stage, int tid) {
    uint32_t sa = sbase + stage * STAGE_B;
    uint32_t sb = sa + 10240;
    #pragma unroll
    for (int i = 0; i < 4; i++) {
        int idx = tid + 128 * i;
        int row = idx >> 2, c = idx & 3;
        const __half* g = A + (long long)row * lda + k0 + c * 8;
        asm volatile("cp.async.cg.shared.global [%0], [%1], 16;"
                     :: "r"(sa + row * 80 + c * 16), "l"(g));
    }
    #pragma unroll
    for (int i = 0; i < 4; i++) {
        int idx = tid + 128 * i;
        int row = idx >> 2, c = idx & 3;
        const __half* g = B + (long long)row * ldb + k0 + c * 8;
        asm volatile("cp.async.cg.shared.global [%0], [%1], 16;"
                     :: "r"(sb + row * 80 + c * 16), "l"(g));
    }
    asm volatile("cp.async.commit_group;" ::: "memory");
}

template <int MODE>
__global__ void __launch_bounds__(128, 2) hgemm(
    const __half* __restrict__ A, int lda, long long sA,
    const __half* __restrict__ B, int ldb, long long sB,
    void* __restrict__ Cv, int ldc, long long sC,
    int K, float alpha, const float* __restrict__ bias,
    float* __restrict__ aux, __half* __restrict__ vout) {

    extern __shared__ char smem[];
    uint32_t sbase = smem_u32(smem);

    const int tid = threadIdx.x;
    const int lane = tid & 31;
    const int wid = tid >> 5;
    const int warpM = wid >> 1;
    const int warpN = wid & 1;
    const int g = lane >> 2, t4 = lane & 3;
    const int l8 = lane & 7, lm = lane >> 3;

    A += blockIdx.z * sA + (long long)blockIdx.y * 128 * lda;
    B += blockIdx.z * sB + (long long)blockIdx.x * 128 * ldb;

    const uint32_t a_off = (uint32_t)(((lm & 1) * 8 + l8) * 80 + (lm >> 1) * 16)
                         + (uint32_t)(warpM * 64) * 80;
    const uint32_t b_off = (uint32_t)(((lm >> 1) * 8 + l8) * 80 + (lm & 1) * 16)
                         + (uint32_t)(warpN * 64) * 80;

    float acc[4][8][4];
    #pragma unroll
    for (int i = 0; i < 4; i++)
        #pragma unroll
        for (int j = 0; j < 8; j++)
            #pragma unroll
            for (int q = 0; q < 4; q++) acc[i][j][q] = 0.f;

    const int S = K / 32;

    #pragma unroll
    for (int s = 0; s < 3; s++)
        hfill(A, B, lda, ldb, s * 32, sbase, s, tid);

    int stage = 0;
    #pragma unroll 1
    for (int s = 0; s < S; s++) {
        const int rem = S - 1 - s;
        if (rem >= 2)      asm volatile("cp.async.wait_group 2;" ::: "memory");
        else if (rem == 1) asm volatile("cp.async.wait_group 1;" ::: "memory");
        else               asm volatile("cp.async.wait_group 0;" ::: "memory");
        __syncthreads();
        if (s + 3 < S) {
            int fstage = stage + 3; if (fstage >= NSTAGE) fstage -= NSTAGE;
            hfill(A, B, lda, ldb, (s + 3) * 32, sbase, fstage, tid);
        }

        const uint32_t sAb = sbase + stage * STAGE_B;
        const uint32_t sBb = sAb + 10240;

        #pragma unroll
        for (int kk = 0; kk < 2; kk++) {
            const uint32_t kadd = kk * 32;
            uint32_t af[4][4];
            #pragma unroll
            for (int mf = 0; mf < 4; mf++) {
                asm volatile("ldmatrix.sync.aligned.m8n8.x4.shared.b16 {%0,%1,%2,%3}, [%4];"
                    : "=r"(af[mf][0]), "=r"(af[mf][1]), "=r"(af[mf][2]), "=r"(af[mf][3])
                    : "r"(sAb + a_off + mf * 1280 + kadd));
            }
            uint32_t bf[8][2];
            #pragma unroll
            for (int p = 0; p < 4; p++) {
                asm volatile("ldmatrix.sync.aligned.m8n8.x4.shared.b16 {%0,%1,%2,%3}, [%4];"
                    : "=r"(bf[2*p][0]), "=r"(bf[2*p][1]), "=r"(bf[2*p+1][0]), "=r"(bf[2*p+1][1])
                    : "r"(sBb + b_off + p * 1280 + kadd));
            }
            #pragma unroll
            for (int mf = 0; mf < 4; mf++)
                #pragma unroll
                for (int nf = 0; nf < 8; nf++) {
                    asm volatile(
                        "mma.sync.aligned.m16n8k16.row.col.f32.f16.f16.f32 "
                        "{%0,%1,%2,%3}, {%4,%5,%6,%7}, {%8,%9}, {%0,%1,%2,%3};"
                        : "+f"(acc[mf][nf][0]), "+f"(acc[mf][nf][1]),
                          "+f"(acc[mf][nf][2]), "+f"(acc[mf][nf][3])
                        : "r"(af[mf][0]), "r"(af[mf][1]), "r"(af[mf][2]), "r"(af[mf][3]),
                          "r"(bf[nf][0]), "r"(bf[nf][1]));
                }
        }
        if (++stage >= NSTAGE) stage = 0;
    }

    const bool vtile = (MODE == 5) && (blockIdx.x >= 8);
    __half* ts = (__half*)smem;          // V-tile transpose staging: [col][row], stride 136
    if (vtile) __syncthreads();          // mainloop smem no longer needed

    const float* bp = bias ? bias + blockIdx.x * 128 : nullptr;
    #pragma unroll
    for (int mf = 0; mf < 4; mf++) {
        const int row = warpM * 64 + mf * 16 + g;
        float r0 = 0.f, r1 = 0.f;
        float inv0 = 1.f, inv1 = 1.f;
        if (MODE == 4) {
            const float* rs = aux + (size_t)blockIdx.z * NSP + blockIdx.y * 128;
            inv0 = 1.f / rs[row];
            inv1 = 1.f / rs[row + 8];
        }
        #pragma unroll
        for (int nf = 0; nf < 8; nf++) {
            const int col = warpN * 64 + nf * 8 + 2 * t4;
            float b0 = 0.f, b1 = 0.f;
            if (bp) { b0 = bp[col]; b1 = bp[col + 1]; }
            float v00 = alpha * acc[mf][nf][0] + b0;
            float v01 = alpha * acc[mf][nf][1] + b1;
            float v10 = alpha * acc[mf][nf][2] + b0;
            float v11 = alpha * acc[mf][nf][3] + b1;
            if (MODE == 0 || MODE == 4 || MODE == 5) {
                if (MODE == 4) { v00 *= inv0; v01 *= inv0; v10 *= inv1; v11 *= inv1; }
                if (vtile) {
                    ts[(col)     * 136 + row]     = __float2half(v00);
                    ts[(col + 1) * 136 + row]     = __float2half(v01);
                    ts[(col)     * 136 + row + 8] = __float2half(v10);
                    ts[(col + 1) * 136 + row + 8] = __float2half(v11);
                } else {
                    __half* C = (__half*)Cv + blockIdx.z * sC
                              + (long long)blockIdx.y * 128 * ldc + blockIdx.x * 128;
                    *(__half2*)(C + (long long)row * ldc + col)       = __floats2half2_rn(v00, v01);
                    *(__half2*)(C + (long long)(row + 8) * ldc + col) = __floats2half2_rn(v10, v11);
                }
            } else if (MODE == 3) {
                float e00 = __expf(v00), e01 = __expf(v01);
                float e10 = __expf(v10), e11 = __expf(v11);
                __half* C = (__half*)Cv + blockIdx.z * sC
                          + (long long)blockIdx.y * 128 * ldc + blockIdx.x * 128;
                *(__half2*)(C + (long long)row * ldc + col)       = __floats2half2_rn(e00, e01);
                *(__half2*)(C + (long long)(row + 8) * ldc + col) = __floats2half2_rn(e10, e11);
                r0 += e00 + e01;
                r1 += e10 + e11;
            } else if (MODE == 2) {
                const int rowg = blockIdx.y * 128 + row;
                const int b  = rowg >> 12;
                const int n  = rowg & (NSP - 1);
                const int c0 = blockIdx.x * 128 + col;
                float* out = (float*)Cv;
                const float* xres = aux;
                size_t base = (size_t)b * CH * NSP + n;
                size_t i00 = base + (size_t)c0 * NSP;
                size_t i01 = base + (size_t)(c0 + 1) * NSP;
                out[i00]     = xres[i00]     + v00;
                out[i01]     = xres[i01]     + v01;
                out[i00 + 8] = xres[i00 + 8] + v10;
                out[i01 + 8] = xres[i01 + 8] + v11;
            }
        }
        if (MODE == 3) {
            r0 += __shfl_xor_sync(0xffffffffu, r0, 1);
            r0 += __shfl_xor_sync(0xffffffffu, r0, 2);
            r1 += __shfl_xor_sync(0xffffffffu, r1, 1);
            r1 += __shfl_xor_sync(0xffffffffu, r1, 2);
            if (t4 == 0) {
                float* rs = aux + (size_t)blockIdx.z * NSP + blockIdx.y * 128;
                atomicAdd(rs + row, r0);
                atomicAdd(rs + row + 8, r1);
            }
        }
    }

    if (vtile) {
        __syncthreads();
        // rows of tile share one batch (128 | 4096): b from blockIdx.y
        const int b  = (blockIdx.y * 128) >> 12;
        const int n0 = (blockIdx.y * 128) & (NSP - 1);
        const int cg = blockIdx.x * 128 - 1024 + tid;   // this thread's channel
        __half* dst = vout + (size_t)b * CH * NSP + (size_t)cg * NSP + n0;
        const __half* src = ts + tid * 136;
        #pragma unroll
        for (int i = 0; i < 16; i++)
            ((uint4*)dst)[i] = ((const uint4*)src)[i];
    }
}

// ---------------- launch ----------------
extern "C" void kernel_launch(void* const* d_in, const int* in_sizes, int n_in,
                              void* d_out, int out_size) {
    const float* x     = (const float*)d_in[0];
    const float* gw    = (const float*)d_in[1];
    const float* gb    = (const float*)d_in[2];
    const float* qkvW  = (const float*)d_in[3];
    const float* qkvB  = (const float*)d_in[4];
    const float* projW = (const float*)d_in[5];
    const float* projB = (const float*)d_in[6];
    float* out = (float*)d_out;

    __half *seqh, *qkvh, *ph, *vth, *attnh, *qkvWh, *projWh;
    float *rowsum, *stats;
    cudaGetSymbolAddress((void**)&seqh,  g_seqh);
    cudaGetSymbolAddress((void**)&qkvh,  g_qkvh);
    cudaGetSymbolAddress((void**)&ph,    g_ph);
    cudaGetSymbolAddress((void**)&vth,   g_vth);
    cudaGetSymbolAddress((void**)&attnh, g_attnh);
    cudaGetSymbolAddress((void**)&qkvWh, g_qkvWh);
    cudaGetSymbolAddress((void**)&projWh,g_projWh);
    cudaGetSymbolAddress((void**)&rowsum,g_rowsum);
    cudaGetSymbolAddress((void**)&stats, g_stats);

    static bool attr_done = false;
    if (!attr_done) {
        cudaFuncSetAttribute((const void*)hgemm<2>,
                             cudaFuncAttributeMaxDynamicSharedMemorySize, HG_SMEM);
        cudaFuncSetAttribute((const void*)hgemm<3>,
                             cudaFuncAttributeMaxDynamicSharedMemorySize, HG_SMEM);
        cudaFuncSetAttribute((const void*)hgemm<4>,
                             cudaFuncAttributeMaxDynamicSharedMemorySize, HG_SMEM);
        cudaFuncSetAttribute((const void*)hgemm<5>,
                             cudaFuncAttributeMaxDynamicSharedMemorySize, HG_SMEM);
        attr_done = true;
    }

    // 1. GroupNorm + weight conversion (+rowsum zero)
    gn_stats_kernel<<<BATCH * NGRP, 256>>>(x, stats);
    wconv_kernel<<<C3 * CH / 1024, 256>>>(qkvW, projW, qkvWh, projWh, rowsum);
    gn_apply_kernel<<<dim3(NSP / 32, CH / 32, BATCH), dim3(32, 8)>>>(x, stats, gw, gb, seqh);

    // 2. QKV projection -> half; V written transposed directly
    hgemm<5><<<dim3(C3 / 128, (BATCH * NSP) / 128, 1), 128, HG_SMEM>>>(
        seqh, CH, 0, qkvWh, CH, 0, qkvh, C3, 0, CH, 1.f, qkvB, nullptr, vth);

    // 3. P = exp(Q K^T * scale) -> half, rowsum accumulated
    const float scale = 0.044194173824159216f;
    hgemm<3><<<dim3(NSP / 128, NSP / 128, BATCH), 128, HG_SMEM>>>(
        qkvh, C3, (long long)NSP * C3,
        qkvh + CH, C3, (long long)NSP * C3,
        ph, NSP, (long long)NSP * NSP,
        CH, scale, nullptr, rowsum, nullptr);

    // 4. O = (P V^T) / rowsum -> half
    hgemm<4><<<dim3(CH / 128, NSP / 128, BATCH), 128, HG_SMEM>>>(
        ph, NSP, (long long)NSP * NSP,
        vth, NSP, (long long)CH * NSP,
        attnh, CH, (long long)NSP * CH,
        NSP, 1.f, nullptr, rowsum, nullptr);

    // 5. Output projection + residual + transpose, fused -> out [b, c, h, w, d]
    hgemm<2><<<dim3(CH / 128, (BATCH * NSP) / 128, 1), 128, HG_SMEM>>>(
        attnh, CH, 0, projWh, CH, 0, out, CH, (long long)CH * NSP, CH, 1.f, projB,
        (float*)x, nullptr);
}